// round 6
// baseline (speedup 1.0000x reference)
#include <cuda_runtime.h>
#include <cuda_fp16.h>
#include <stdint.h>

#define NHEADS 16
#define DMODEL 2048
#define DHEAD  128
#define ROTD   64
#define BATCHN 4
#define SEQL   2048
#define MTOT   (BATCHN*SEQL)     /* 8192 */
#define KTOT   DMODEL            /* 2048 */
#define NSEG   (NHEADS*DHEAD)    /* 2048 */
#define NTOT   (3*NSEG)          /* 6144 */

#define BM 128
#define BN 128
#define BK 64
#define STAGES 3
#define THREADS 256

#define RES_F4  ((MTOT*DMODEL)/4)            /* 4194304 float4 */
#define GRID_X  (NTOT/BN)                    /* 48 */
#define GRID_Y  (MTOT/BM)                    /* 64 */
#define RSTRIDE (GRID_X*GRID_Y*THREADS)      /* 786432 */

// ---- scratch (device globals: no allocation allowed) ----
__device__ __half g_Xh[(size_t)MTOT * KTOT];   // x in fp16, row-major [M][K]
__device__ __half g_Wh[(size_t)NTOT * KTOT];   // packed B^T in fp16, [N][K]
__device__ float2 g_rope[SEQL * (ROTD / 2)];   // (cos, sin) per (pos, pair)

// ------------------------------------------------------------------
// Fused prologue: one launch, three independent block segments
//   [0, 2048)        : fp32 x -> fp16  (each block: 2048 float4)
//   [2048, 14336)    : pack W_{Q,K,V} [16,2048,128] -> g_Wh [6144][2048]
//   [14336, 14400)   : rotary table
// ------------------------------------------------------------------
#define PRO_CONV_BLKS 2048
#define PRO_PACK_BLKS 12288
#define PRO_ROPE_BLKS 64
#define PRO_BLKS (PRO_CONV_BLKS + PRO_PACK_BLKS + PRO_ROPE_BLKS)

__global__ void __launch_bounds__(256)
prologue_kernel(const float4* __restrict__ x,
                const float* __restrict__ Wq,
                const float* __restrict__ Wk,
                const float* __restrict__ Wv) {
    __shared__ float t[32][33];
    const int bid = blockIdx.x;
    const int tid = threadIdx.x;

    if (bid < PRO_CONV_BLKS) {
        // ---- convert x: fp32 -> fp16 ----
        int base = bid * 2048 + tid;
#pragma unroll
        for (int j = 0; j < 8; j++) {
            float4 v = x[base + j * 256];
            __half2 h0 = __floats2half2_rn(v.x, v.y);
            __half2 h1 = __floats2half2_rn(v.z, v.w);
            uint2 u;
            u.x = *reinterpret_cast<uint32_t*>(&h0);
            u.y = *reinterpret_cast<uint32_t*>(&h1);
            reinterpret_cast<uint2*>(g_Xh)[base + j * 256] = u;
        }
    } else if (bid < PRO_CONV_BLKS + PRO_PACK_BLKS) {
        // ---- pack W (transpose d<->e per head) ----
        int pid = bid - PRO_CONV_BLKS;
        int z   = pid >> 8;          // 0..47
        int rem = pid & 255;
        int d0  = (rem & 63) * 32;   // DMODEL/32 = 64
        int e0  = (rem >> 6) * 32;   // DHEAD/32  = 4
        int h   = z & 15;
        int seg = z >> 4;
        const float* W = (seg == 0) ? Wq : (seg == 1) ? Wk : Wv;
        const float* base = W + (size_t)h * DMODEL * DHEAD;
        int tx = tid & 31, ty = tid >> 5;   // 32 x 8
#pragma unroll
        for (int i = 0; i < 4; i++) {
            int dl = ty + i * 8;
            t[dl][tx] = base[(size_t)(d0 + dl) * DHEAD + e0 + tx];
        }
        __syncthreads();
#pragma unroll
        for (int i = 0; i < 4; i++) {
            int el = ty + i * 8;
            int n  = seg * NSEG + h * DHEAD + e0 + el;
            g_Wh[(size_t)n * KTOT + d0 + tx] = __float2half_rn(t[tx][el]);
        }
    } else {
        // ---- rotary table (double precision trig) ----
        int b2 = bid - (PRO_CONV_BLKS + PRO_PACK_BLKS);
#pragma unroll
        for (int j = 0; j < 4; j++) {
            int i = b2 * 1024 + j * 256 + tid;   // [0, 65536)
            int pos = i >> 5;                     // ROTD/2 == 32
            int jj  = i & 31;
            double freq = exp(log(10000.0) * (double)jj / 32.0);
            double a = (double)pos / freq;
            g_rope[i] = make_float2((float)cos(a), (float)sin(a));
        }
    }
}

// ------------------------------------------------------------------
// Main fused GEMM + bias + rotary + residual copy
// ------------------------------------------------------------------
__device__ __forceinline__ uint32_t smem_u32(const void* p) {
    uint32_t a;
    asm("{.reg .u64 t; cvta.to.shared.u64 t, %1; cvt.u32.u64 %0, t;}"
        : "=r"(a) : "l"(p));
    return a;
}

extern "C" __global__ void __launch_bounds__(THREADS, 2)
qkv_gemm_kernel(const float* __restrict__ residual,
                const float* __restrict__ bQ, const float* __restrict__ bK,
                const float* __restrict__ bV, float* __restrict__ out) {
    extern __shared__ __half smem[];
    const uint32_t As_u = smem_u32(smem);
    const uint32_t Bs_u = As_u + STAGES * (BM * BK * 2);

    const int tid  = threadIdx.x;
    const int lane = tid & 31;
    const int warp = tid >> 5;
    const int wm = warp & 1;   // 0..1 -> m offset *64
    const int wn = warp >> 1;  // 0..3 -> n offset *32

    const int m0 = blockIdx.y * BM;
    const int n0 = blockIdx.x * BN;
    const int seg = n0 / NSEG;          // 0=q 1=k 2=v (block uniform)
    const int w0  = n0 - seg * NSEG;    // column within segment (mult of 128)

    auto load_stage = [&](int stg, int k0) {
        uint32_t abase = As_u + stg * (BM * BK * 2);
        uint32_t bbase = Bs_u + stg * (BN * BK * 2);
#pragma unroll
        for (int i = 0; i < 4; i++) {
            int id  = tid + i * THREADS;   // 0..1023
            int row = id >> 3;
            int c   = id & 7;
            int ch  = c ^ (row & 7);       // SW128 swizzle
            const __half* srcA = &g_Xh[(size_t)(m0 + row) * KTOT + k0 + c * 8];
            uint32_t dstA = abase + row * 128 + (ch << 4);
            asm volatile("cp.async.cg.shared.global [%0], [%1], 16;\n"
                         :: "r"(dstA), "l"(srcA) : "memory");
            const __half* srcB = &g_Wh[(size_t)(n0 + row) * KTOT + k0 + c * 8];
            uint32_t dstB = bbase + row * 128 + (ch << 4);
            asm volatile("cp.async.cg.shared.global [%0], [%1], 16;\n"
                         :: "r"(dstB), "l"(srcB) : "memory");
        }
    };

    float acc[4][4][4];
#pragma unroll
    for (int i = 0; i < 4; i++)
#pragma unroll
        for (int j = 0; j < 4; j++)
#pragma unroll
            for (int k = 0; k < 4; k++) acc[i][j][k] = 0.f;

    load_stage(0, 0);
    asm volatile("cp.async.commit_group;\n" ::: "memory");
    load_stage(1, BK);
    asm volatile("cp.async.commit_group;\n" ::: "memory");

    // ---- residual passthrough, hidden in the GEMM's memory slack ----
    {
        const float4* rsrc = reinterpret_cast<const float4*>(residual);
        float4* rdst = reinterpret_cast<float4*>(out);
        int rid = (blockIdx.y * GRID_X + blockIdx.x) * THREADS + tid;
#pragma unroll
        for (int j = 0; j < 6; j++) {
            int idx = rid + j * RSTRIDE;
            if (idx < RES_F4) rdst[idx] = rsrc[idx];
        }
    }

    const int KITERS = KTOT / BK;  // 32
    for (int kt = 0; kt < KITERS; kt++) {
        asm volatile("cp.async.wait_group 1;\n" ::: "memory");
        __syncthreads();
        if (kt + 2 < KITERS) load_stage((kt + 2) % STAGES, (kt + 2) * BK);
        asm volatile("cp.async.commit_group;\n" ::: "memory");

        uint32_t a_st = As_u + (kt % STAGES) * (BM * BK * 2);
        uint32_t b_st = Bs_u + (kt % STAGES) * (BN * BK * 2);
#pragma unroll
        for (int ks = 0; ks < 4; ks++) {
            uint32_t a[4][4];
            uint32_t b[4][2];
#pragma unroll
            for (int mt = 0; mt < 4; mt++) {
                int r  = wm * 64 + mt * 16 + (lane & 15);
                int ch = (ks * 2 + (lane >> 4)) ^ (r & 7);
                uint32_t addr = a_st + r * 128 + (ch << 4);
                asm volatile(
                    "ldmatrix.sync.aligned.m8n8.x4.shared.b16 {%0,%1,%2,%3}, [%4];"
                    : "=r"(a[mt][0]), "=r"(a[mt][1]), "=r"(a[mt][2]), "=r"(a[mt][3])
                    : "r"(addr));
            }
#pragma unroll
            for (int bt = 0; bt < 2; bt++) {
                int n  = wn * 32 + bt * 16 + (lane & 15);
                int ch = (ks * 2 + (lane >> 4)) ^ (n & 7);
                uint32_t addr = b_st + n * 128 + (ch << 4);
                uint32_t r0, r1, r2, r3;
                asm volatile(
                    "ldmatrix.sync.aligned.m8n8.x4.shared.b16 {%0,%1,%2,%3}, [%4];"
                    : "=r"(r0), "=r"(r1), "=r"(r2), "=r"(r3)
                    : "r"(addr));
                b[bt * 2][0] = r0; b[bt * 2][1] = r2;
                b[bt * 2 + 1][0] = r1; b[bt * 2 + 1][1] = r3;
            }
#pragma unroll
            for (int mt = 0; mt < 4; mt++)
#pragma unroll
                for (int nt = 0; nt < 4; nt++)
                    asm volatile(
                        "mma.sync.aligned.m16n8k16.row.col.f32.f16.f16.f32 "
                        "{%0,%1,%2,%3}, {%4,%5,%6,%7}, {%8,%9}, {%0,%1,%2,%3};"
                        : "+f"(acc[mt][nt][0]), "+f"(acc[mt][nt][1]),
                          "+f"(acc[mt][nt][2]), "+f"(acc[mt][nt][3])
                        : "r"(a[mt][0]), "r"(a[mt][1]), "r"(a[mt][2]), "r"(a[mt][3]),
                          "r"(b[nt][0]), "r"(b[nt][1]));
        }
    }

    // -------- epilogue: bias + rotary, stage via smem, coalesced store ----
    __syncthreads();
    float* tile = reinterpret_cast<float*>(smem);  // [128][136]
    const float* bias = (seg == 0) ? bQ : (seg == 1) ? bK : bV;

#pragma unroll
    for (int mt = 0; mt < 4; mt++) {
#pragma unroll
        for (int nt = 0; nt < 4; nt++) {
            int c = wn * 32 + nt * 8 + ((lane & 3) << 1);   // block-local col (== e)
            float bv0 = bias[w0 + c];
            float bv1 = bias[w0 + c + 1];
#pragma unroll
            for (int hh = 0; hh < 2; hh++) {
                int r = wm * 64 + mt * 16 + (lane >> 2) + hh * 8;
                float v0 = acc[mt][nt][hh * 2 + 0] + bv0;
                float v1 = acc[mt][nt][hh * 2 + 1] + bv1;
                if (seg < 2 && c < ROTD) {
                    int pos = (m0 + r) & (SEQL - 1);
                    float2 cs = g_rope[pos * (ROTD / 2) + (c >> 1)];
                    float t0 = v0 * cs.x - v1 * cs.y;
                    v1 = v1 * cs.x + v0 * cs.y;
                    v0 = t0;
                }
                tile[r * 136 + c]     = v0;
                tile[r * 136 + c + 1] = v1;
            }
        }
    }
    __syncthreads();

    size_t obase = (size_t)(1 + seg) * ((size_t)MTOT * NSEG);
#pragma unroll
    for (int it = 0; it < 16; it++) {
        int id  = tid + it * THREADS;
        int row = id >> 5;
        int c4  = (id & 31) << 2;
        float4 v = *reinterpret_cast<float4*>(&tile[row * 136 + c4]);
        *reinterpret_cast<float4*>(
            &out[obase + (size_t)(m0 + row) * NSEG + w0 + c4]) = v;
    }
}

// ------------------------------------------------------------------
// Launch
// ------------------------------------------------------------------
extern "C" void kernel_launch(void* const* d_in, const int* in_sizes, int n_in,
                              void* d_out, int out_size) {
    const float* residual = (const float*)d_in[0];
    const float* x  = (const float*)d_in[1];
    const float* Wq = (const float*)d_in[2];
    const float* Wk = (const float*)d_in[3];
    const float* Wv = (const float*)d_in[4];
    const float* bQ = (const float*)d_in[5];
    const float* bK = (const float*)d_in[6];
    const float* bV = (const float*)d_in[7];
    float* out = (float*)d_out;

    cudaFuncSetAttribute(qkv_gemm_kernel,
                         cudaFuncAttributeMaxDynamicSharedMemorySize,
                         STAGES * (BM + BN) * BK * (int)sizeof(__half));

    // fused prologue (convert + pack + rope), one launch
    prologue_kernel<<<PRO_BLKS, 256>>>(
        reinterpret_cast<const float4*>(x), Wq, Wk, Wv);

    // fused GEMM + bias + rotary + residual copy
    dim3 grid(GRID_X, GRID_Y);
    qkv_gemm_kernel<<<grid, THREADS,
                      STAGES * (BM + BN) * BK * sizeof(__half)>>>(
        residual, bQ, bK, bV, out);
}

// round 8
// speedup vs baseline: 1.0355x; 1.0355x over previous
#include <cuda_runtime.h>
#include <cuda_fp16.h>
#include <stdint.h>

#define NHEADS 16
#define DMODEL 2048
#define DHEAD  128
#define ROTD   64
#define BATCHN 4
#define SEQL   2048
#define MTOT   (BATCHN*SEQL)     /* 8192 */
#define KTOT   DMODEL            /* 2048 */
#define NSEG   (NHEADS*DHEAD)    /* 2048 */
#define NTOT   (3*NSEG)          /* 6144 */

#define BM 128
#define BN 128
#define BK 64
#define STAGES 3
#define THREADS 256

#define RES_F4  ((MTOT*DMODEL)/4)            /* 4194304 float4 */
#define GRID_X  (NTOT/BN)                    /* 48 */
#define GRID_Y  (MTOT/BM)                    /* 64 */
#define RSTRIDE (GRID_X*GRID_Y*THREADS)      /* 786432 */

// ---- scratch (device globals: no allocation allowed) ----
__device__ __half g_Xh[(size_t)MTOT * KTOT];   // x in fp16, row-major [M][K]
__device__ __half g_Wh[(size_t)NTOT * KTOT];   // packed B^T in fp16, [N][K]
__device__ float2 g_rope[SEQL * (ROTD / 2)];   // (cos, sin) per (pos, pair)

// ------------------------------------------------------------------
// Prologue: fp32 x -> fp16
// ------------------------------------------------------------------
__global__ void convert_x_kernel(const float4* __restrict__ x, int n4) {
    int i = blockIdx.x * blockDim.x + threadIdx.x;
    if (i < n4) {
        float4 v = x[i];
        __half2 h0 = __floats2half2_rn(v.x, v.y);
        __half2 h1 = __floats2half2_rn(v.z, v.w);
        uint2 u;
        u.x = *reinterpret_cast<uint32_t*>(&h0);
        u.y = *reinterpret_cast<uint32_t*>(&h1);
        reinterpret_cast<uint2*>(g_Xh)[i] = u;
    }
}

// ------------------------------------------------------------------
// Prologue: pack W_{Q,K,V} [16,2048,128] -> g_Wh [6144][2048] fp16
// ------------------------------------------------------------------
__global__ void pack_w_kernel(const float* __restrict__ Wq,
                              const float* __restrict__ Wk,
                              const float* __restrict__ Wv) {
    __shared__ float t[32][33];
    int h   = blockIdx.z & 15;
    int seg = blockIdx.z >> 4;
    const float* W = (seg == 0) ? Wq : (seg == 1) ? Wk : Wv;
    const float* base = W + (size_t)h * DMODEL * DHEAD;
    int d0 = blockIdx.x * 32;
    int e0 = blockIdx.y * 32;
    int tx = threadIdx.x, ty = threadIdx.y;
#pragma unroll
    for (int i = 0; i < 4; i++) {
        int dl = ty + i * 8;
        t[dl][tx] = base[(size_t)(d0 + dl) * DHEAD + e0 + tx];
    }
    __syncthreads();
#pragma unroll
    for (int i = 0; i < 4; i++) {
        int el = ty + i * 8;
        int n  = seg * NSEG + h * DHEAD + e0 + el;
        g_Wh[(size_t)n * KTOT + d0 + tx] = __float2half_rn(t[tx][el]);
    }
}

// ------------------------------------------------------------------
// Prologue: rotary table (double precision trig)
// ------------------------------------------------------------------
__global__ void rope_table_kernel() {
    int i = blockIdx.x * blockDim.x + threadIdx.x;
    if (i < SEQL * (ROTD / 2)) {
        int pos = i >> 5;        // ROTD/2 == 32
        int j   = i & 31;
        double freq = exp(log(10000.0) * (double)j / 32.0);
        double a = (double)pos / freq;
        g_rope[i] = make_float2((float)cos(a), (float)sin(a));
    }
}

// ------------------------------------------------------------------
// Main fused GEMM + bias + rotary + residual copy
// ------------------------------------------------------------------
__device__ __forceinline__ uint32_t smem_u32(const void* p) {
    uint32_t a;
    asm("{.reg .u64 t; cvta.to.shared.u64 t, %1; cvt.u32.u64 %0, t;}"
        : "=r"(a) : "l"(p));
    return a;
}

#define LDMX4(addr, r0, r1, r2, r3) \
    asm volatile("ldmatrix.sync.aligned.m8n8.x4.shared.b16 {%0,%1,%2,%3}, [%4];" \
                 : "=r"(r0), "=r"(r1), "=r"(r2), "=r"(r3) : "r"(addr))

extern "C" __global__ void __launch_bounds__(THREADS, 2)
qkv_gemm_kernel(const float* __restrict__ residual,
                const float* __restrict__ bQ, const float* __restrict__ bK,
                const float* __restrict__ bV, float* __restrict__ out) {
    extern __shared__ __half smem[];
    const uint32_t As_u = smem_u32(smem);
    const uint32_t Bs_u = As_u + STAGES * (BM * BK * 2);

    const int tid  = threadIdx.x;
    const int lane = tid & 31;
    const int warp = tid >> 5;
    const int wm = warp & 1;   // 0..1 -> m offset *64
    const int wn = warp >> 1;  // 0..3 -> n offset *32

    const int m0 = blockIdx.y * BM;
    const int n0 = blockIdx.x * BN;
    const int seg = n0 / NSEG;          // 0=q 1=k 2=v (block uniform)
    const int w0  = n0 - seg * NSEG;    // column within segment (mult of 128)

    // precomputed ldmatrix row-base offsets (swizzle XOR uses lane&7 only,
    // since row%8 == lane%8 for all fragments here)
    const int lx7 = (lane & 7) << 4;
    const int kx0 = (lane >> 4);        // column-halves selector
    uint32_t r128a[4], r128b[2];
#pragma unroll
    for (int mt = 0; mt < 4; mt++)
        r128a[mt] = (wm * 64 + mt * 16 + (lane & 15)) * 128;
#pragma unroll
    for (int bt = 0; bt < 2; bt++)
        r128b[bt] = (wn * 32 + bt * 16 + (lane & 15)) * 128;

    auto load_stage = [&](int stg, int k0) {
        uint32_t abase = As_u + stg * (BM * BK * 2);
        uint32_t bbase = Bs_u + stg * (BN * BK * 2);
#pragma unroll
        for (int i = 0; i < 4; i++) {
            int id  = tid + i * THREADS;   // 0..1023
            int row = id >> 3;
            int c   = id & 7;
            int ch  = c ^ (row & 7);       // SW128 swizzle
            const __half* srcA = &g_Xh[(size_t)(m0 + row) * KTOT + k0 + c * 8];
            asm volatile("cp.async.cg.shared.global [%0], [%1], 16;\n"
                         :: "r"(abase + row * 128 + (ch << 4)), "l"(srcA) : "memory");
            const __half* srcB = &g_Wh[(size_t)(n0 + row) * KTOT + k0 + c * 8];
            asm volatile("cp.async.cg.shared.global [%0], [%1], 16;\n"
                         :: "r"(bbase + row * 128 + (ch << 4)), "l"(srcB) : "memory");
        }
    };

    float acc[4][4][4];
#pragma unroll
    for (int i = 0; i < 4; i++)
#pragma unroll
        for (int j = 0; j < 4; j++)
#pragma unroll
            for (int k = 0; k < 4; k++) acc[i][j][k] = 0.f;

    load_stage(0, 0);
    asm volatile("cp.async.commit_group;\n" ::: "memory");
    load_stage(1, BK);
    asm volatile("cp.async.commit_group;\n" ::: "memory");

    // ---- residual passthrough, hidden in the GEMM's memory slack ----
    {
        const float4* rsrc = reinterpret_cast<const float4*>(residual);
        float4* rdst = reinterpret_cast<float4*>(out);
        int rid = (blockIdx.y * GRID_X + blockIdx.x) * THREADS + tid;
#pragma unroll
        for (int j = 0; j < 6; j++) {
            int idx = rid + j * RSTRIDE;
            if (idx < RES_F4) rdst[idx] = rsrc[idx];
        }
    }

    uint32_t fa[2][4][4], fb[2][4][2];

    // fragment loader for one k16 slice (ks in 0..3) of stage bases
    auto load_frags = [&](uint32_t a_st, uint32_t b_st, int ks,
                          uint32_t (*A)[4], uint32_t (*B)[2]) {
        int chA = (((ks * 2 + kx0)) << 4);  // pre-XOR column offset
#pragma unroll
        for (int mt = 0; mt < 4; mt++) {
            uint32_t addr = a_st + r128a[mt] + (chA ^ lx7);
            LDMX4(addr, A[mt][0], A[mt][1], A[mt][2], A[mt][3]);
        }
#pragma unroll
        for (int bt = 0; bt < 2; bt++) {
            uint32_t addr = b_st + r128b[bt] + (chA ^ lx7);
            uint32_t r0, r1, r2, r3;
            LDMX4(addr, r0, r1, r2, r3);
            B[bt * 2][0] = r0;     B[bt * 2][1] = r2;
            B[bt * 2 + 1][0] = r1; B[bt * 2 + 1][1] = r3;
        }
    };

    auto do_mma = [&](uint32_t (*A)[4], uint32_t (*B)[2]) {
#pragma unroll
        for (int mt = 0; mt < 4; mt++)
#pragma unroll
            for (int nt = 0; nt < 4; nt++)
                asm volatile(
                    "mma.sync.aligned.m16n8k16.row.col.f32.f16.f16.f32 "
                    "{%0,%1,%2,%3}, {%4,%5,%6,%7}, {%8,%9}, {%0,%1,%2,%3};"
                    : "+f"(acc[mt][nt][0]), "+f"(acc[mt][nt][1]),
                      "+f"(acc[mt][nt][2]), "+f"(acc[mt][nt][3])
                    : "r"(A[mt][0]), "r"(A[mt][1]), "r"(A[mt][2]), "r"(A[mt][3]),
                      "r"(B[nt][0]), "r"(B[nt][1]));
    };

    const int KITERS = KTOT / BK;  // 32
    for (int kt = 0; kt < KITERS; kt++) {
        asm volatile("cp.async.wait_group 1;\n" ::: "memory");
        __syncthreads();
        if (kt + 2 < KITERS) load_stage((kt + 2) % STAGES, (kt + 2) * BK);
        asm volatile("cp.async.commit_group;\n" ::: "memory");

        uint32_t a_st = As_u + (kt % STAGES) * (BM * BK * 2);
        uint32_t b_st = Bs_u + (kt % STAGES) * (BN * BK * 2);

        // software-pipelined fragments: ld(ks+1) overlaps mma(ks)
        load_frags(a_st, b_st, 0, fa[0], fb[0]);
        load_frags(a_st, b_st, 1, fa[1], fb[1]);
        do_mma(fa[0], fb[0]);
        load_frags(a_st, b_st, 2, fa[0], fb[0]);
        do_mma(fa[1], fb[1]);
        load_frags(a_st, b_st, 3, fa[1], fb[1]);
        do_mma(fa[0], fb[0]);
        do_mma(fa[1], fb[1]);
    }

    // -------- epilogue: bias + rotary, direct float2 stores ----
    const float* bias = (seg == 0) ? bQ : (seg == 1) ? bK : bV;
    const int cp = (lane & 3) << 1;   // column pair offset within nt block

    // hoist bias (4 nt positions, 2 floats each)
    float2 bv[4];
#pragma unroll
    for (int nt = 0; nt < 4; nt++) {
        int c = wn * 32 + nt * 8 + cp;
        bv[nt] = *reinterpret_cast<const float2*>(&bias[w0 + c]);
    }

    size_t obase = (size_t)(1 + seg) * ((size_t)MTOT * NSEG);
#pragma unroll
    for (int mt = 0; mt < 4; mt++) {
#pragma unroll
        for (int hh = 0; hh < 2; hh++) {
            int rl  = wm * 64 + mt * 16 + (lane >> 2) + hh * 8;
            int pos = (m0 + rl) & (SEQL - 1);
            float* orow = &out[obase + (size_t)(m0 + rl) * NSEG + w0];
#pragma unroll
            for (int nt = 0; nt < 4; nt++) {
                int c = wn * 32 + nt * 8 + cp;
                float v0 = acc[mt][nt][hh * 2 + 0] + bv[nt].x;
                float v1 = acc[mt][nt][hh * 2 + 1] + bv[nt].y;
                if (seg < 2 && c < ROTD) {
                    float2 cs = g_rope[pos * (ROTD / 2) + (c >> 1)];
                    float t0 = v0 * cs.x - v1 * cs.y;
                    v1 = v1 * cs.x + v0 * cs.y;
                    v0 = t0;
                }
                *reinterpret_cast<float2*>(&orow[c]) = make_float2(v0, v1);
            }
        }
    }
}

// ------------------------------------------------------------------
// Launch
// ------------------------------------------------------------------
extern "C" void kernel_launch(void* const* d_in, const int* in_sizes, int n_in,
                              void* d_out, int out_size) {
    const float* residual = (const float*)d_in[0];
    const float* x  = (const float*)d_in[1];
    const float* Wq = (const float*)d_in[2];
    const float* Wk = (const float*)d_in[3];
    const float* Wv = (const float*)d_in[4];
    const float* bQ = (const float*)d_in[5];
    const float* bK = (const float*)d_in[6];
    const float* bV = (const float*)d_in[7];
    float* out = (float*)d_out;

    cudaFuncSetAttribute(qkv_gemm_kernel,
                         cudaFuncAttributeMaxDynamicSharedMemorySize,
                         STAGES * (BM + BN) * BK * (int)sizeof(__half));

    // prologues (separate kernels — measured faster than the fused variant)
    int n4 = (MTOT * KTOT) / 4;
    convert_x_kernel<<<(n4 + 255) / 256, 256>>>(
        reinterpret_cast<const float4*>(x), n4);
    dim3 pw_grid(DMODEL / 32, DHEAD / 32, 48);
    pack_w_kernel<<<pw_grid, dim3(32, 8)>>>(Wq, Wk, Wv);
    rope_table_kernel<<<(SEQL * (ROTD / 2) + 255) / 256, 256>>>();

    // fused GEMM + bias + rotary + residual copy
    dim3 grid(GRID_X, GRID_Y);
    qkv_gemm_kernel<<<grid, THREADS,
                      STAGES * (BM + BN) * BK * sizeof(__half)>>>(
        residual, bQ, bK, bV, out);
}